// round 7
// baseline (speedup 1.0000x reference)
#include <cuda_runtime.h>
#include <cuda_bf16.h>

// ThermoQuantizer: groupwise abs-mean scale + softmax quantization onto a
// uniform 16-level codebook + lerp.
//
// Key observation: qxn(xn) is a smooth 1-D function (codebook/temp fixed per
// launch). Each block builds a 2048-segment linear-interp LUT of qxn over
// xn in [-12, 12] (covers all reachable xn: mean|xn|=1 by construction) using
// the exact palindromic-Horner evaluation, then the hot loop is one LDS.64 +
// ~10 ALU/FMA ops per element with ZERO MUFU. Memory-roofline bound.
//
// Exact path for table build: p_k ∝ G_k R^k, R = 2^(xn*K2); symmetric codebook
//   => den = (R+1) R^7 Q(z), num = (R-1) R^7 S(z), z = R + 1/R (Q,S deg 7);
//   qxn = (R-1)S(z) / ((R+1)Q(z)). Coefficients via warp-0 shfl-scan.
//
// Persistent single wave: 152 SM x 5 blocks x 256 thr, 1 warp = 2 groups
// (half-warp per group), 8 elems/thread, packed f32x2 epilogue.

typedef unsigned long long ull;
#define FULL_MASK 0xFFFFFFFFu

#define TAB_N    2048
#define TAB_XMIN -12.0f
#define TAB_INVH (2048.0f / 24.0f)     // 85.3333...
#define TAB_OFF  1024.0f               // -XMIN * INVH
#define TAB_UMAX 2047.999f

// Basis-transform columns: row j (0..7) holds T[t][j] for t=1..7, where
// t_t(z) = R^t + R^-t expanded in powers of z.
__device__ const float gTcol[56] = {
    0.f,-2.f, 0.f,  2.f, 0.f,-2.f, 0.f,   // j=0
    1.f, 0.f,-3.f,  0.f, 5.f, 0.f,-7.f,   // j=1
    0.f, 1.f, 0.f, -4.f, 0.f, 9.f, 0.f,   // j=2
    0.f, 0.f, 1.f,  0.f,-5.f, 0.f,14.f,   // j=3
    0.f, 0.f, 0.f,  1.f, 0.f,-6.f, 0.f,   // j=4
    0.f, 0.f, 0.f,  0.f, 1.f, 0.f,-7.f,   // j=5
    0.f, 0.f, 0.f,  0.f, 0.f, 1.f, 0.f,   // j=6
    0.f, 0.f, 0.f,  0.f, 0.f, 0.f, 1.f};  // j=7

__device__ __forceinline__ ull pk2(float lo, float hi) {
    ull r; asm("mov.b64 %0, {%1, %2};" : "=l"(r) : "f"(lo), "f"(hi)); return r;
}
__device__ __forceinline__ void upk2(ull v, float& lo, float& hi) {
    asm("mov.b64 {%0, %1}, %2;" : "=f"(lo), "=f"(hi) : "l"(v));
}
__device__ __forceinline__ ull fma2(ull a, ull b, ull c) {
    ull d; asm("fma.rn.f32x2 %0, %1, %2, %3;" : "=l"(d) : "l"(a), "l"(b), "l"(c)); return d;
}
__device__ __forceinline__ ull mul2(ull a, ull b) {
    ull d; asm("mul.rn.f32x2 %0, %1, %2;" : "=l"(d) : "l"(a), "l"(b)); return d;
}
__device__ __forceinline__ float ex2f(float a) {
    float r; asm("ex2.approx.ftz.f32 %0, %1;" : "=f"(r) : "f"(a)); return r;
}
__device__ __forceinline__ float rcpf(float a) {
    float r; asm("rcp.approx.ftz.f32 %0, %1;" : "=f"(r) : "f"(a)); return r;
}

__global__ __launch_bounds__(256, 5) void ThermoQuantizer_50122268345057_kernel(
    const float* __restrict__ x,
    const float* __restrict__ cb,
    const float* __restrict__ pp,
    const float* __restrict__ pt,
    float* __restrict__ out,
    int n4)
{
    __shared__ ull   sTab[TAB_N];        // packed (f_i, f_{i+1}-f_i)
    __shared__ float sF[TAB_N + 1];      // node values (build scratch)
    __shared__ ull   sC[16];             // (q_j,q_j) j=0..7 then (s_j,s_j)
    __shared__ float sK2, sPres;

    const int tid = threadIdx.x;

    // ---- stage 1: Q,S coefficient derivation (warp 0, lane-parallel) ----
    if (tid < 32) {
        const int lane = tid;
        const int k = lane & 15;
        const float invT = 1.0f / (pt[0] + 1e-6f);
        const float c = cb[k];
        const float g = __expf(-c * c * invT);
        const float Hk = g * c;

        // p[j] = (-1)^j * prefixsum((-1)^i G_i);  m[j] = -prefixsum(H_i)
        float sg = (k & 1) ? -g : g;
        float sh = Hk;
        #pragma unroll
        for (int o = 1; o <= 8; o <<= 1) {
            float tg = __shfl_up_sync(FULL_MASK, sg, o);
            float th = __shfl_up_sync(FULL_MASK, sh, o);
            if (lane >= o) { sg += tg; sh += th; }
        }
        const float pv = (k & 1) ? -sg : sg;
        const float mv = -sh;

        float pb[8], mb[8];
        #pragma unroll
        for (int t = 0; t < 8; ++t) {
            pb[t] = __shfl_sync(FULL_MASK, pv, 7 + t);
            mb[t] = __shfl_sync(FULL_MASK, mv, 7 + t);
        }

        if (lane < 8) {
            float q = (lane == 0) ? pb[0] : 0.f;
            float s = (lane == 0) ? mb[0] : 0.f;
            const float* Tc = &gTcol[lane * 7];
            #pragma unroll
            for (int t = 1; t <= 7; ++t) {
                float tc = Tc[t - 1];
                q = fmaf(pb[t], tc, q);
                s = fmaf(mb[t], tc, s);
            }
            sC[lane]     = pk2(q, q);
            sC[lane + 8] = pk2(s, s);
        }
        if (lane == 0) {
            sK2 = 2.0f * (cb[1] - cb[0]) * invT * 1.4426950408889634f;
            sPres = pp[0];
        }
    }
    __syncthreads();

    // ---- stage 2: build qxn table nodes (all 256 threads) ----
    {
        const float* sCf = reinterpret_cast<const float*>(sC);
        const float K2 = sK2;
        for (int i = tid; i <= TAB_N; i += 256) {
            float xn = TAB_XMIN + (float)i * (1.0f / TAB_INVH);
            float a = xn * K2;
            a = fminf(fmaxf(a, -10.0f), 10.0f);
            float r = ex2f(a);
            float z = r + rcpf(r);
            float accq = sCf[14], accs = sCf[30];
            #pragma unroll
            for (int j = 6; j >= 0; --j) {
                accq = fmaf(accq, z, sCf[2 * j]);
                accs = fmaf(accs, z, sCf[16 + 2 * j]);
            }
            float den = (r + 1.0f) * accq;
            float num = (r - 1.0f) * accs;
            sF[i] = num * rcpf(den);
        }
    }
    __syncthreads();
    for (int i = tid; i < TAB_N; i += 256)
        sTab[i] = pk2(sF[i], sF[i + 1] - sF[i]);
    __syncthreads();

    // ---- stage 3: persistent tile loop (1 warp = 2 groups, 8 elems/thr) ----
    const int lane = tid & 31;
    const int h = lane >> 4;
    const int ql = lane & 15;
    const int warpsTotal = gridDim.x * 8;
    const int wId = blockIdx.x * 8 + (tid >> 5);
    const int numTiles = (n4 + 63) >> 6;

    const float pres = sPres;
    const float onemp = 1.0f - pres;
    const ull om2 = pk2(onemp, onemp);

    const float4* __restrict__ x4 = reinterpret_cast<const float4*>(x);
    float4* __restrict__ o4 = reinterpret_cast<float4*>(out);

    for (int tile = wId; tile < numTiles; tile += warpsTotal) {
        const int qb = tile * 64 + h * 32 + ql;
        const bool vld = (qb + 16) <= n4;      // group whole-or-absent
        float4 a0, a1;
        if (vld) { a0 = x4[qb]; a1 = x4[qb + 16]; }
        else     { a0 = make_float4(0.f,0.f,0.f,0.f); a1 = a0; }

        // group abs-mean over this 16-lane half (128 elements)
        float ss = (fabsf(a0.x) + fabsf(a0.y)) + (fabsf(a0.z) + fabsf(a0.w))
                 + (fabsf(a1.x) + fabsf(a1.y)) + (fabsf(a1.z) + fabsf(a1.w));
        ss += __shfl_xor_sync(FULL_MASK, ss, 8);
        ss += __shfl_xor_sync(FULL_MASK, ss, 4);
        ss += __shfl_xor_sync(FULL_MASK, ss, 2);
        ss += __shfl_xor_sync(FULL_MASK, ss, 1);
        const float mean_c = fmaxf(ss * (1.0f / 128.0f), 1e-5f);
        const float uScale = TAB_INVH * rcpf(mean_c);   // xn index scale
        const float pm = pres * mean_c;
        const ull pm2 = pk2(pm, pm);

        const float xs[8] = {a0.x, a0.y, a0.z, a0.w, a1.x, a1.y, a1.z, a1.w};

        // per-element: u = x*uScale + OFF; LUT lookup + linear interp
        float qv[8];
        #pragma unroll
        for (int e = 0; e < 8; ++e) {
            float u = fmaf(xs[e], uScale, TAB_OFF);
            u = fminf(fmaxf(u, 0.0f), TAB_UMAX);
            int idx = (int)u;
            float frac = u - (float)idx;
            float f, d; upk2(sTab[idx], f, d);
            qv[e] = fmaf(frac, d, f);
        }

        // out = (1-p)*x + p*mean*qxn   (packed pairs)
        if (vld) {
            float resv[8];
            #pragma unroll
            for (int pI = 0; pI < 4; ++pI) {
                ull xpP = pk2(xs[2 * pI], xs[2 * pI + 1]);
                ull qP  = pk2(qv[2 * pI], qv[2 * pI + 1]);
                ull resP = fma2(pm2, qP, mul2(om2, xpP));
                upk2(resP, resv[2 * pI], resv[2 * pI + 1]);
            }
            o4[qb]      = make_float4(resv[0], resv[1], resv[2], resv[3]);
            o4[qb + 16] = make_float4(resv[4], resv[5], resv[6], resv[7]);
        }
    }
}

extern "C" void kernel_launch(void* const* d_in, const int* in_sizes, int n_in,
                              void* d_out, int out_size) {
    const float* x  = (const float*)d_in[0];
    const float* cbk = (const float*)d_in[1];
    const float* pr = (const float*)d_in[2];
    const float* tp = (const float*)d_in[3];
    float* out = (float*)d_out;

    const int n4 = out_size / 4;               // float4 quads
    const int numTiles = (n4 + 63) >> 6;
    int blocks = 152 * 5;                      // one resident wave
    const int maxBlocks = (numTiles + 7) / 8;  // 8 warps/block
    if (blocks > maxBlocks) blocks = maxBlocks;
    if (blocks < 1) blocks = 1;
    ThermoQuantizer_50122268345057_kernel<<<blocks, 256>>>(x, cbk, pr, tp, out, n4);
}

// round 10
// speedup vs baseline: 1.0719x; 1.0719x over previous
#include <cuda_runtime.h>
#include <cuda_bf16.h>

// ThermoQuantizer: groupwise abs-mean scale + softmax quantization onto a
// uniform 16-level codebook + lerp.
//
// qxn(xn) is a smooth 1-D function (codebook/temp fixed per launch): each
// block builds a 2048-segment linear-interp LUT of qxn over xn in [-12,12]
// via the exact palindromic-Horner evaluation; the hot loop is one LDS.64 +
// ~8 ALU/FMA per element, zero MUFU.
//
// Round-9: retest the two memory-path levers (round 8 failed to compile only
// because redux.sync.add.f32 is not supported on sm_103a -> reverted to the
// proven 4-shfl butterfly on 16-lane halves):
//   - ld.global.cs / st.global.cs streaming hints (single-touch data; stop
//     the 64MB write stream from thrashing the read stream in L2)
//   - register double-buffer prefetch: next tile's loads issued before the
//     current tile's compute -> loads continuously in flight per warp
//
// Persistent single wave, 1 warp = 2 groups (half-warp per group), 8 elems/thr.

typedef unsigned long long ull;
#define FULL_MASK 0xFFFFFFFFu

#define TAB_N    2048
#define TAB_XMIN -12.0f
#define TAB_INVH (2048.0f / 24.0f)
#define TAB_OFF  1024.0f
#define TAB_UMAX 2047.999f

__device__ const float gTcol[56] = {
    0.f,-2.f, 0.f,  2.f, 0.f,-2.f, 0.f,   // j=0
    1.f, 0.f,-3.f,  0.f, 5.f, 0.f,-7.f,   // j=1
    0.f, 1.f, 0.f, -4.f, 0.f, 9.f, 0.f,   // j=2
    0.f, 0.f, 1.f,  0.f,-5.f, 0.f,14.f,   // j=3
    0.f, 0.f, 0.f,  1.f, 0.f,-6.f, 0.f,   // j=4
    0.f, 0.f, 0.f,  0.f, 1.f, 0.f,-7.f,   // j=5
    0.f, 0.f, 0.f,  0.f, 0.f, 1.f, 0.f,   // j=6
    0.f, 0.f, 0.f,  0.f, 0.f, 0.f, 1.f};  // j=7

__device__ __forceinline__ ull pk2(float lo, float hi) {
    ull r; asm("mov.b64 %0, {%1, %2};" : "=l"(r) : "f"(lo), "f"(hi)); return r;
}
__device__ __forceinline__ void upk2(ull v, float& lo, float& hi) {
    asm("mov.b64 {%0, %1}, %2;" : "=f"(lo), "=f"(hi) : "l"(v));
}
__device__ __forceinline__ ull fma2(ull a, ull b, ull c) {
    ull d; asm("fma.rn.f32x2 %0, %1, %2, %3;" : "=l"(d) : "l"(a), "l"(b), "l"(c)); return d;
}
__device__ __forceinline__ ull mul2(ull a, ull b) {
    ull d; asm("mul.rn.f32x2 %0, %1, %2;" : "=l"(d) : "l"(a), "l"(b)); return d;
}
__device__ __forceinline__ float ex2f(float a) {
    float r; asm("ex2.approx.ftz.f32 %0, %1;" : "=f"(r) : "f"(a)); return r;
}
__device__ __forceinline__ float rcpf(float a) {
    float r; asm("rcp.approx.ftz.f32 %0, %1;" : "=f"(r) : "f"(a)); return r;
}
// streaming (evict-first) global load/store, 128-bit
__device__ __forceinline__ float4 ldcs4(const float4* p) {
    float4 v;
    asm("ld.global.cs.v4.f32 {%0,%1,%2,%3}, [%4];"
        : "=f"(v.x), "=f"(v.y), "=f"(v.z), "=f"(v.w) : "l"(p));
    return v;
}
__device__ __forceinline__ void stcs4(float4* p, float4 v) {
    asm volatile("st.global.cs.v4.f32 [%0], {%1,%2,%3,%4};"
                 :: "l"(p), "f"(v.x), "f"(v.y), "f"(v.z), "f"(v.w) : "memory");
}

__global__ __launch_bounds__(256, 4) void ThermoQuantizer_50122268345057_kernel(
    const float* __restrict__ x,
    const float* __restrict__ cb,
    const float* __restrict__ pp,
    const float* __restrict__ pt,
    float* __restrict__ out,
    int n4)
{
    __shared__ ull   sTab[TAB_N];        // packed (f_i, f_{i+1}-f_i)
    __shared__ float sF[TAB_N + 1];      // node values (build scratch)
    __shared__ ull   sC[16];             // (q_j,q_j) j=0..7 then (s_j,s_j)
    __shared__ float sK2, sPres;

    const int tid = threadIdx.x;

    // ---- stage 1: Q,S coefficient derivation (warp 0, lane-parallel) ----
    if (tid < 32) {
        const int lane0 = tid;
        const int k = lane0 & 15;
        const float invT = 1.0f / (pt[0] + 1e-6f);
        const float c = cb[k];
        const float g = __expf(-c * c * invT);
        const float Hk = g * c;

        float sg = (k & 1) ? -g : g;     // p: alternating prefix sum
        float sh = Hk;                   // m: plain prefix sum (negated)
        #pragma unroll
        for (int o = 1; o <= 8; o <<= 1) {
            float tg = __shfl_up_sync(FULL_MASK, sg, o);
            float th = __shfl_up_sync(FULL_MASK, sh, o);
            if (lane0 >= o) { sg += tg; sh += th; }
        }
        const float pv = (k & 1) ? -sg : sg;
        const float mv = -sh;

        float pb[8], mb[8];
        #pragma unroll
        for (int t = 0; t < 8; ++t) {
            pb[t] = __shfl_sync(FULL_MASK, pv, 7 + t);
            mb[t] = __shfl_sync(FULL_MASK, mv, 7 + t);
        }
        if (lane0 < 8) {
            float q = (lane0 == 0) ? pb[0] : 0.f;
            float s = (lane0 == 0) ? mb[0] : 0.f;
            const float* Tc = &gTcol[lane0 * 7];
            #pragma unroll
            for (int t = 1; t <= 7; ++t) {
                float tc = Tc[t - 1];
                q = fmaf(pb[t], tc, q);
                s = fmaf(mb[t], tc, s);
            }
            sC[lane0]     = pk2(q, q);
            sC[lane0 + 8] = pk2(s, s);
        }
        if (lane0 == 0) {
            sK2 = 2.0f * (cb[1] - cb[0]) * invT * 1.4426950408889634f;
            sPres = pp[0];
        }
    }
    __syncthreads();

    // ---- stage 2: build qxn table (all 256 threads) ----
    {
        const float* sCf = reinterpret_cast<const float*>(sC);
        const float K2 = sK2;
        for (int i = tid; i <= TAB_N; i += 256) {
            float xn = TAB_XMIN + (float)i * (1.0f / TAB_INVH);
            float a = fminf(fmaxf(xn * K2, -10.0f), 10.0f);
            float r = ex2f(a);
            float z = r + rcpf(r);
            float accq = sCf[14], accs = sCf[30];
            #pragma unroll
            for (int j = 6; j >= 0; --j) {
                accq = fmaf(accq, z, sCf[2 * j]);
                accs = fmaf(accs, z, sCf[16 + 2 * j]);
            }
            float den = (r + 1.0f) * accq;
            float num = (r - 1.0f) * accs;
            sF[i] = num * rcpf(den);
        }
    }
    __syncthreads();
    for (int i = tid; i < TAB_N; i += 256)
        sTab[i] = pk2(sF[i], sF[i + 1] - sF[i]);
    __syncthreads();

    // ---- stage 3: persistent loop, double-buffered streaming ----
    const int lane = tid & 31;
    const int h = lane >> 4;
    const int ql = lane & 15;
    const int warpsTotal = gridDim.x * 8;
    const int wId = blockIdx.x * 8 + (tid >> 5);
    const int numTiles = (n4 + 63) >> 6;

    const float pres = sPres;
    const float onemp = 1.0f - pres;
    const ull om2 = pk2(onemp, onemp);

    const float4* __restrict__ x4 = reinterpret_cast<const float4*>(x);
    float4* __restrict__ o4 = reinterpret_cast<float4*>(out);

    int tile = wId;
    bool vld = tile < numTiles;
    int qb = tile * 64 + h * 32 + ql;
    float4 a0 = make_float4(0.f, 0.f, 0.f, 0.f), a1 = a0;
    if (vld && (qb + 16) <= n4) { a0 = ldcs4(x4 + qb); a1 = ldcs4(x4 + qb + 16); }

    #pragma unroll 1
    while (vld) {
        // prefetch next tile before touching current data
        const int ntile = tile + warpsTotal;
        const bool nvld = ntile < numTiles;
        int nqb = 0;
        float4 b0 = make_float4(0.f, 0.f, 0.f, 0.f), b1 = b0;
        if (nvld) {
            nqb = ntile * 64 + h * 32 + ql;
            if ((nqb + 16) <= n4) { b0 = ldcs4(x4 + nqb); b1 = ldcs4(x4 + nqb + 16); }
        }

        // group abs-mean over this 16-lane half (128 elements)
        float ss = (fabsf(a0.x) + fabsf(a0.y)) + (fabsf(a0.z) + fabsf(a0.w))
                 + (fabsf(a1.x) + fabsf(a1.y)) + (fabsf(a1.z) + fabsf(a1.w));
        ss += __shfl_xor_sync(FULL_MASK, ss, 8);
        ss += __shfl_xor_sync(FULL_MASK, ss, 4);
        ss += __shfl_xor_sync(FULL_MASK, ss, 2);
        ss += __shfl_xor_sync(FULL_MASK, ss, 1);
        const float mean_c = fmaxf(ss * (1.0f / 128.0f), 1e-5f);
        const float uScale = TAB_INVH * rcpf(mean_c);
        const float pm = pres * mean_c;
        const ull pm2 = pk2(pm, pm);

        const float xs[8] = {a0.x, a0.y, a0.z, a0.w, a1.x, a1.y, a1.z, a1.w};

        float qv[8];
        #pragma unroll
        for (int e = 0; e < 8; ++e) {
            float u = fmaf(xs[e], uScale, TAB_OFF);
            u = fminf(fmaxf(u, 0.0f), TAB_UMAX);
            int idx = (int)u;
            float frac = u - (float)idx;
            float f, d; upk2(sTab[idx], f, d);
            qv[e] = fmaf(frac, d, f);
        }

        if ((qb + 16) <= n4) {
            float resv[8];
            #pragma unroll
            for (int pI = 0; pI < 4; ++pI) {
                ull xpP = pk2(xs[2 * pI], xs[2 * pI + 1]);
                ull qP  = pk2(qv[2 * pI], qv[2 * pI + 1]);
                ull resP = fma2(pm2, qP, mul2(om2, xpP));
                upk2(resP, resv[2 * pI], resv[2 * pI + 1]);
            }
            stcs4(o4 + qb,      make_float4(resv[0], resv[1], resv[2], resv[3]));
            stcs4(o4 + qb + 16, make_float4(resv[4], resv[5], resv[6], resv[7]));
        }

        tile = ntile; qb = nqb; vld = nvld; a0 = b0; a1 = b1;
    }
}

extern "C" void kernel_launch(void* const* d_in, const int* in_sizes, int n_in,
                              void* d_out, int out_size) {
    const float* x  = (const float*)d_in[0];
    const float* cbk = (const float*)d_in[1];
    const float* pr = (const float*)d_in[2];
    const float* tp = (const float*)d_in[3];
    float* out = (float*)d_out;

    const int n4 = out_size / 4;               // float4 quads
    const int numTiles = (n4 + 63) >> 6;
    int blocks = 152 * 4;                      // one resident wave at 4 blocks/SM
    const int maxBlocks = (numTiles + 7) / 8;  // 8 warps/block
    if (blocks > maxBlocks) blocks = maxBlocks;
    if (blocks < 1) blocks = 1;
    ThermoQuantizer_50122268345057_kernel<<<blocks, 256>>>(x, cbk, pr, tp, out, n4);
}